// round 13
// baseline (speedup 1.0000x reference)
#include <cuda_runtime.h>

#define NB 16
#define NC 3
#define IH 720
#define IW 1280
#define OUT 255
#define PER_B (NC*IH*IW)          /* 2764800 floats per batch image */
#define PER_B4 (PER_B/4)          /* 691200 float4 per batch image */
#define NRED 736                  /* reduce blocks (5 per SM) */
#define NBIL 448                  /* bilinear blocks (3 per SM) */
#define NBLK (NRED+NBIL)          /* 1184 = exactly 8 per SM, all resident */
#define SWEEP (NRED*256)          /* 188416 float4 per full sweep */
#define TAIL  (PER_B4 - 3*SWEEP)  /* 125952: threads with i0 < TAIL do a 4th load */
#define NTILE (NB*OUT)            /* 4080 output rows */

__device__ float d_partial[NB * NRED];
__device__ float d_mean[NB];
__device__ unsigned int d_bcount[NB];   /* wrapping per-batch counters (replay-safe) */
__device__ volatile int d_bflag[NB];    /* batch b mean ready + data L2-resident */

// ---------------------------------------------------------------------------
// Fused persistent kernel.
//  bid < NRED : reduce role — sweeps batches IN ORDER; last block per batch
//               finalizes mean_b and releases flag_b.
//  bid >= NRED: bilinear role — processes row-tiles in increasing batch order,
//               waiting on flag_b, then single-pass blend with avg (L2-hot).
// ---------------------------------------------------------------------------
__global__ void __launch_bounds__(256, 8)
fused_kernel(const float* __restrict__ im,
             const float* __restrict__ pos,
             const float* __restrict__ szs,
             float* __restrict__ out) {
    const int bid = blockIdx.x;
    const int tid = threadIdx.x;

    if (bid < NRED) {
        /* ==================== REDUCE ROLE ==================== */
        __shared__ float smw[8];
        __shared__ int s_last;
        const int i0 = bid * 256 + tid;            /* 0..188415 */
        const int w = tid >> 5, l = tid & 31;

        #pragma unroll 1
        for (int b = 0; b < NB; b++) {
            const float4* __restrict__ p = (const float4*)(im + (size_t)b * PER_B);

            /* 3.668 sweeps per batch: 3 full + partial 4th */
            float4 v0 = p[i0];
            float4 v1 = p[i0 + SWEEP];
            float4 v2 = p[i0 + 2 * SWEEP];
            float a0 = (v0.x + v0.y) + (v0.z + v0.w);
            float a1 = (v1.x + v1.y) + (v1.z + v1.w);
            float a2 = (v2.x + v2.y) + (v2.z + v2.w);
            float a3 = 0.0f;
            if (i0 < TAIL) {
                float4 v3 = p[i0 + 3 * SWEEP];
                a3 = (v3.x + v3.y) + (v3.z + v3.w);
            }
            float s = (a0 + a1) + (a2 + a3);

            #pragma unroll
            for (int o = 16; o > 0; o >>= 1) s += __shfl_down_sync(0xffffffffu, s, o);
            if (l == 0) smw[w] = s;
            __syncthreads();

            if (tid == 0) {
                float bs = ((smw[0] + smw[1]) + (smw[2] + smw[3])) +
                           ((smw[4] + smw[5]) + (smw[6] + smw[7]));
                d_partial[b * NRED + bid] = bs;
                __threadfence();
                unsigned int old = atomicInc(&d_bcount[b], NRED - 1);
                s_last = (old == NRED - 1);
            }
            __syncthreads();            /* also protects smw reuse below */

            if (s_last) {
                /* block-wide finalize of batch b: sum 736 partials */
                const float* pp = &d_partial[b * NRED];
                float s2 = __ldcg(&pp[tid]) + __ldcg(&pp[tid + 256]);
                if (tid < NRED - 512) s2 += __ldcg(&pp[tid + 512]);
                #pragma unroll
                for (int o = 16; o > 0; o >>= 1)
                    s2 += __shfl_down_sync(0xffffffffu, s2, o);
                if (l == 0) smw[w] = s2;
                __syncthreads();
                if (tid == 0) {
                    float tot = ((smw[0] + smw[1]) + (smw[2] + smw[3])) +
                                ((smw[4] + smw[5]) + (smw[6] + smw[7]));
                    d_mean[b] = tot * (1.0f / (float)PER_B);
                    __threadfence();
                    d_bflag[b] = 1;
                }
            }
            __syncthreads();
        }
    } else {
        /* ==================== BILINEAR ROLE ==================== */
        const int bb = bid - NRED;                 /* 0..447 */
        const int ox = tid;
        const bool act = (ox < OUT);

        int   lastb = -1;
        float avg = 0.0f;

        #pragma unroll 1
        for (int k = 0;; k++) {
            int t = bb + k * NBIL;                 /* increasing -> batch order */
            if (t >= NTILE) break;
            int b2 = t / OUT;
            int oy = t - b2 * OUT;

            if (b2 != lastb) {
                if (tid == 0) {
                    while (d_bflag[b2] == 0) __nanosleep(256);
                }
                __syncthreads();                   /* block-uniform condition */
                avg = __ldcg(&d_mean[b2]);
                lastb = b2;
            }

            if (act) {
                const float sz    = __ldg(&szs[b2]);
                const float half  = (sz + 1.0f) * 0.5f;
                const float xmin  = rintf(__ldg(&pos[2 * b2 + 0]) - half);  /* jnp.round */
                const float ymin  = rintf(__ldg(&pos[2 * b2 + 1]) - half);
                const float scale = sz / (float)OUT;
                const float szm1  = sz - 1.0f;

                float sx = fminf(fmaxf(((float)ox + 0.5f) * scale - 0.5f, 0.0f), szm1);
                float lx = floorf(sx);
                float wx = sx - lx;
                float hx = fminf(lx + 1.0f, szm1);

                float sy = fminf(fmaxf(((float)oy + 0.5f) * scale - 0.5f, 0.0f), szm1);
                float ly = floorf(sy);
                float wy = sy - ly;
                float hy = fminf(ly + 1.0f, szm1);

                float y0 = ly + ymin, y1 = hy + ymin;
                float x0 = lx + xmin, x1 = hx + xmin;

                bool vy0 = (y0 >= 0.0f) & (y0 <= (float)(IH - 1));
                bool vy1 = (y1 >= 0.0f) & (y1 <= (float)(IH - 1));
                bool vx0 = (x0 >= 0.0f) & (x0 <= (float)(IW - 1));
                bool vx1 = (x1 >= 0.0f) & (x1 <= (float)(IW - 1));
                int iy0 = (int)fminf(fmaxf(y0, 0.0f), (float)(IH - 1));
                int iy1 = (int)fminf(fmaxf(y1, 0.0f), (float)(IH - 1));
                int ix0 = (int)fminf(fmaxf(x0, 0.0f), (float)(IW - 1));
                int ix1 = (int)fminf(fmaxf(x1, 0.0f), (float)(IW - 1));
                bool v00 = vy0 & vx0, v01 = vy0 & vx1;
                bool v10 = vy1 & vx0, v11 = vy1 & vx1;

                const int o00 = iy0 * IW + ix0;
                const int o01 = iy0 * IW + ix1;
                const int o10 = iy1 * IW + ix0;
                const int o11 = iy1 * IW + ix1;

                const float omwx = 1.0f - wx, omwy = 1.0f - wy;
                const float* base = im + (size_t)b2 * PER_B;
                float* orow = out + ((size_t)(b2 * NC) * OUT + oy) * OUT + ox;

                #pragma unroll
                for (int c = 0; c < NC; c++) {
                    const float* pl = base + c * (IH * IW);
                    float p00 = v00 ? __ldg(&pl[o00]) : avg;
                    float p01 = v01 ? __ldg(&pl[o01]) : avg;
                    float p10 = v10 ? __ldg(&pl[o10]) : avg;
                    float p11 = v11 ? __ldg(&pl[o11]) : avg;
                    orow[c * (OUT * OUT)] =
                        (p00 * omwx + p01 * wx) * omwy +
                        (p10 * omwx + p11 * wx) * wy;
                }
            }
        }
    }
}

// ---------------------------------------------------------------------------
extern "C" void kernel_launch(void* const* d_in, const int* in_sizes, int n_in,
                              void* d_out, int out_size) {
    const float* im  = (const float*)d_in[0];
    const float* pos = (const float*)d_in[1];
    const float* szs = (const float*)d_in[2];
    float* out = (float*)d_out;

    fused_kernel<<<NBLK, 256>>>(im, pos, szs, out);
}

// round 14
// speedup vs baseline: 1.4273x; 1.4273x over previous
#include <cuda_runtime.h>

#define NB 16
#define NC 3
#define IH 720
#define IW 1280
#define OUT 255
#define PER_B (NC*IH*IW)          /* 2764800 floats per batch image */
#define PER_B4 (PER_B/4)          /* 691200 float4 per batch image */
#define RBLK 56                   /* reduce blocks per batch */
#define NRED (RBLK*NB)            /* 896 blocks ~ 6/SM: ALL resident, 2 slots/SM free */
#define RSTRIDE (RBLK*256)        /* 14336 float4 per sweep */
#define NFULL 48                  /* full sweeps: 48*14336 = 688128 */
#define NTILE (NB*OUT)            /* 4080 output rows */

__device__ float d_partial[NRED];
__device__ float d_mean[NB];
__device__ unsigned int d_count = 0;   /* wrapping counter -> graph-replay safe */
__device__ volatile int d_flag = 0;    /* means-ready release flag */

// ---------------------------------------------------------------------------
// Kernel A (hi-prio stream, 896 blocks = ~6/SM, all resident at t=0):
// per-batch partial sums; last block finalizes all 16 means + sets flag.
// ---------------------------------------------------------------------------
__global__ void __launch_bounds__(256, 8)
reduce_kernel(const float* __restrict__ im) {
    const int b   = blockIdx.y;
    const int blk = blockIdx.x;
    const int tid = threadIdx.x;
    const float4* __restrict__ p = (const float4*)(im + (size_t)b * PER_B);
    const int i0 = blk * 256 + tid;

    float a0 = 0.f, a1 = 0.f, a2 = 0.f, a3 = 0.f;
    #pragma unroll 3
    for (int j = 0; j < NFULL; j += 4) {         /* 12 quads, always in bounds */
        int i = i0 + j * RSTRIDE;
        float4 v0 = p[i];
        float4 v1 = p[i + RSTRIDE];
        float4 v2 = p[i + 2 * RSTRIDE];
        float4 v3 = p[i + 3 * RSTRIDE];
        a0 += (v0.x + v0.y) + (v0.z + v0.w);
        a1 += (v1.x + v1.y) + (v1.z + v1.w);
        a2 += (v2.x + v2.y) + (v2.z + v2.w);
        a3 += (v3.x + v3.y) + (v3.z + v3.w);
    }
    {
        int i = i0 + NFULL * RSTRIDE;            /* remainder: 3072 float4 */
        if (i < PER_B4) {
            float4 v = p[i];
            a0 += (v.x + v.y) + (v.z + v.w);
        }
    }
    float s = (a0 + a1) + (a2 + a3);

    __shared__ float smw[8];
    #pragma unroll
    for (int o = 16; o > 0; o >>= 1) s += __shfl_down_sync(0xffffffffu, s, o);
    const int w = tid >> 5, l = tid & 31;
    if (l == 0) smw[w] = s;
    __syncthreads();

    if (w == 0) {
        int last = 0;
        if (l == 0) {
            float bs = ((smw[0] + smw[1]) + (smw[2] + smw[3])) +
                       ((smw[4] + smw[5]) + (smw[6] + smw[7]));
            d_partial[b * RBLK + blk] = bs;
            __threadfence();
            unsigned int old = atomicInc(&d_count, NRED - 1);
            last = (old == NRED - 1);
        }
        last = __shfl_sync(0xffffffffu, last, 0);
        if (last) {
            /* single warp finalizes all 16 means (56 partials each, L2-hot) */
            #pragma unroll 1
            for (int bb = 0; bb < NB; bb++) {
                const float* pp = &d_partial[bb * RBLK];
                float s2 = __ldcg(&pp[l]);
                if (l < RBLK - 32) s2 += __ldcg(&pp[l + 32]);
                #pragma unroll
                for (int o = 16; o > 0; o >>= 1)
                    s2 += __shfl_down_sync(0xffffffffu, s2, o);
                if (l == 0) d_mean[bb] = s2 * (1.0f / (float)PER_B);
            }
            if (l == 0) {
                __threadfence();
                atomicExch((int*)&d_flag, 1);
            }
        }
    }
}

// ---------------------------------------------------------------------------
// Kernel B (default stream): bilinear, one row per block, streams through the
// ~2 free slots/SM during the reduce. Valid blend held in registers; only
// OOB-containing blocks spin on the flag before the single store.
// ---------------------------------------------------------------------------
__global__ void __launch_bounds__(256, 8)
bilinear_kernel(const float* __restrict__ im,
                const float* __restrict__ pos,
                const float* __restrict__ szs,
                float* __restrict__ out) {
    const int oy = blockIdx.x;
    const int b  = blockIdx.y;
    const int ox = threadIdx.x;
    const bool act = (ox < OUT);

    float w_inv = 0.0f;
    float r0 = 0.f, r1 = 0.f, r2 = 0.f;

    if (act) {
        const float sz    = __ldg(&szs[b]);
        const float half  = (sz + 1.0f) * 0.5f;
        const float xmin  = rintf(__ldg(&pos[2 * b + 0]) - half);  /* jnp.round */
        const float ymin  = rintf(__ldg(&pos[2 * b + 1]) - half);
        const float scale = sz / (float)OUT;
        const float szm1  = sz - 1.0f;

        float sx = fminf(fmaxf(((float)ox + 0.5f) * scale - 0.5f, 0.0f), szm1);
        float lx = floorf(sx);
        float wx = sx - lx;
        float hx = fminf(lx + 1.0f, szm1);

        float sy = fminf(fmaxf(((float)oy + 0.5f) * scale - 0.5f, 0.0f), szm1);
        float ly = floorf(sy);
        float wy = sy - ly;
        float hy = fminf(ly + 1.0f, szm1);

        float y0 = ly + ymin, y1 = hy + ymin;
        float x0 = lx + xmin, x1 = hx + xmin;

        bool vy0 = (y0 >= 0.0f) & (y0 <= (float)(IH - 1));
        bool vy1 = (y1 >= 0.0f) & (y1 <= (float)(IH - 1));
        bool vx0 = (x0 >= 0.0f) & (x0 <= (float)(IW - 1));
        bool vx1 = (x1 >= 0.0f) & (x1 <= (float)(IW - 1));
        int iy0 = (int)fminf(fmaxf(y0, 0.0f), (float)(IH - 1));
        int iy1 = (int)fminf(fmaxf(y1, 0.0f), (float)(IH - 1));
        int ix0 = (int)fminf(fmaxf(x0, 0.0f), (float)(IW - 1));
        int ix1 = (int)fminf(fmaxf(x1, 0.0f), (float)(IW - 1));
        bool v00 = vy0 & vx0, v01 = vy0 & vx1, v10 = vy1 & vx0, v11 = vy1 & vx1;

        const int o00 = iy0 * IW + ix0;
        const int o01 = iy0 * IW + ix1;
        const int o10 = iy1 * IW + ix0;
        const int o11 = iy1 * IW + ix1;

        const float omwx = 1.0f - wx, omwy = 1.0f - wy;
        const float w00 = omwx * omwy, w01 = wx * omwy;
        const float w10 = omwx * wy,  w11 = wx * wy;
        w_inv = (v00 ? 0.0f : w00) + (v01 ? 0.0f : w01) +
                (v10 ? 0.0f : w10) + (v11 ? 0.0f : w11);

        const float* base = im + (size_t)b * PER_B;
        {
            const float* pl = base;
            float p00 = v00 ? __ldg(&pl[o00]) : 0.0f;
            float p01 = v01 ? __ldg(&pl[o01]) : 0.0f;
            float p10 = v10 ? __ldg(&pl[o10]) : 0.0f;
            float p11 = v11 ? __ldg(&pl[o11]) : 0.0f;
            r0 = (p00 * omwx + p01 * wx) * omwy + (p10 * omwx + p11 * wx) * wy;
        }
        {
            const float* pl = base + IH * IW;
            float p00 = v00 ? __ldg(&pl[o00]) : 0.0f;
            float p01 = v01 ? __ldg(&pl[o01]) : 0.0f;
            float p10 = v10 ? __ldg(&pl[o10]) : 0.0f;
            float p11 = v11 ? __ldg(&pl[o11]) : 0.0f;
            r1 = (p00 * omwx + p01 * wx) * omwy + (p10 * omwx + p11 * wx) * wy;
        }
        {
            const float* pl = base + 2 * (IH * IW);
            float p00 = v00 ? __ldg(&pl[o00]) : 0.0f;
            float p01 = v01 ? __ldg(&pl[o01]) : 0.0f;
            float p10 = v10 ? __ldg(&pl[o10]) : 0.0f;
            float p11 = v11 ? __ldg(&pl[o11]) : 0.0f;
            r2 = (p00 * omwx + p01 * wx) * omwy + (p10 * omwx + p11 * wx) * wy;
        }
    }

    /* block-level join: only OOB-touching blocks wait for the mean */
    int need = __syncthreads_or((w_inv > 0.0f) ? 1 : 0);
    if (need) {
        if (threadIdx.x == 0) {
            while (d_flag == 0) __nanosleep(200);
        }
        __syncthreads();
        if (act && w_inv > 0.0f) {
            float add = w_inv * __ldcg(&d_mean[b]);
            r0 += add; r1 += add; r2 += add;
        }
    }

    if (act) {
        float* orow = out + ((size_t)(b * NC) * OUT + oy) * OUT + ox;
        orow[0]             = r0;
        orow[OUT * OUT]     = r1;
        orow[2 * OUT * OUT] = r2;
    }
}

// ---------------------------------------------------------------------------
extern "C" void kernel_launch(void* const* d_in, const int* in_sizes, int n_in,
                              void* d_out, int out_size) {
    const float* im  = (const float*)d_in[0];
    const float* pos = (const float*)d_in[1];
    const float* szs = (const float*)d_in[2];
    float* out = (float*)d_out;

    int prio_lo, prio_hi;
    cudaDeviceGetStreamPriorityRange(&prio_lo, &prio_hi);

    cudaStream_t s_hi;
    cudaEvent_t e_fork, e_join;
    cudaStreamCreateWithPriority(&s_hi, cudaStreamNonBlocking, prio_hi);
    cudaEventCreateWithFlags(&e_fork, cudaEventDisableTiming);
    cudaEventCreateWithFlags(&e_join, cudaEventDisableTiming);

    /* fork: 896-block reduce on hi-prio stream — ALL its blocks resident at
       t=0 (6/SM), so the flag is always produced; ~2 slots/SM remain for the
       bilinear blocks to stream through concurrently. */
    cudaEventRecord(e_fork, 0);
    cudaStreamWaitEvent(s_hi, e_fork, 0);
    reduce_kernel<<<dim3(RBLK, NB), 256, 0, s_hi>>>(im);
    cudaEventRecord(e_join, s_hi);

    bilinear_kernel<<<dim3(OUT, NB), 256>>>(im, pos, szs, out);

    cudaStreamWaitEvent(0, e_join, 0);
}